// round 14
// baseline (speedup 1.0000x reference)
#include <cuda_runtime.h>
#include <cstdint>

#define BN_SCALEF 0.9995003746877732f
#define LRELU(v) ((v) > 0.f ? (v) : 0.2f * (v))

typedef unsigned long long ull;

// ---------------- f32x2 packed helpers ----------------
__device__ __forceinline__ ull pack2same(float x) {
    ull r; asm("mov.b64 %0, {%1, %1};" : "=l"(r) : "f"(x)); return r;
}
__device__ __forceinline__ void ffma2(ull& d, ull a, ull b) {
    asm("fma.rn.f32x2 %0, %1, %2, %0;" : "+l"(d) : "l"(a), "l"(b));
}
__device__ __forceinline__ void unpack2(ull v, float& lo, float& hi) {
    asm("mov.b64 {%0, %1}, %2;" : "=f"(lo), "=f"(hi) : "l"(v));
}
__device__ __forceinline__ float getc(float4 v, int i) {
    switch (i) { case 0: return v.x; case 1: return v.y; case 2: return v.z; default: return v.w; }
}

// ---------------- scratch (device globals; no allocation) ----------------
__device__ __align__(16) float g_buf0[4 * 256 * 256 * 32];
__device__ __align__(16) float g_buf1[4 * 128 * 128 * 32];
__device__ __align__(16) float g_buf2[4 * 64 * 64 * 32];
__device__ __align__(16) float g_buf3[4 * 64 * 64 * 32];
__device__ __align__(16) float g_disp[4 * 64 * 64 * 2];

// ------ layer 0: conv 3x3 (2->32) + BN + lrelu + pool; 2x2 tile x 16co ----
__global__ __launch_bounds__(128) void conv_pool_first(
    const float* __restrict__ fixedp, const float* __restrict__ movingp,
    float* __restrict__ out, const float* __restrict__ w)
{
    __shared__ __align__(16) float ws[9 * 2 * 32];
    for (int i = threadIdx.x; i < 576; i += blockDim.x) ws[i] = w[i];
    __syncthreads();

    const int H = 512, W = 512, Hp = 256, Wp = 256;
    int t = blockIdx.x * blockDim.x + threadIdx.x;
    int r = t & 1, q = t >> 1;
    int ox = q % Wp; int tmp = q / Wp; int oy = tmp % Hp; int b = tmp / Hp;
    int cy0 = oy * 2, cx0 = ox * 2;

    float xin[2][4][4];
    const float* fb = fixedp  + (size_t)b * H * W;
    const float* mb = movingp + (size_t)b * H * W;
#pragma unroll
    for (int dy = 0; dy < 4; dy++) {
        int iy = cy0 - 1 + dy;
        bool vy = (iy >= 0) && (iy < H);
#pragma unroll
        for (int dx = 0; dx < 4; dx++) {
            int ix = cx0 - 1 + dx;
            bool v = vy && (ix >= 0) && (ix < W);
            xin[0][dy][dx] = v ? __ldg(fb + (size_t)iy * W + ix) : 0.f;
            xin[1][dy][dx] = v ? __ldg(mb + (size_t)iy * W + ix) : 0.f;
        }
    }

    ull acc[2][2][8];
#pragma unroll
    for (int py = 0; py < 2; py++)
#pragma unroll
        for (int px = 0; px < 2; px++)
#pragma unroll
            for (int j = 0; j < 8; j++) acc[py][px][j] = 0ull;

#pragma unroll
    for (int ky = 0; ky < 3; ky++)
#pragma unroll
        for (int kx = 0; kx < 3; kx++)
#pragma unroll
            for (int ci = 0; ci < 2; ci++) {
                const ulonglong2* wp =
                    (const ulonglong2*)&ws[((ky * 3 + kx) * 2 + ci) * 32 + r * 16];
                ulonglong2 wa = wp[0], wb = wp[1], wc = wp[2], wd = wp[3];
#pragma unroll
                for (int py = 0; py < 2; py++)
#pragma unroll
                    for (int px = 0; px < 2; px++) {
                        ull x = pack2same(xin[ci][ky + py][kx + px]);
                        ffma2(acc[py][px][0], x, wa.x);
                        ffma2(acc[py][px][1], x, wa.y);
                        ffma2(acc[py][px][2], x, wb.x);
                        ffma2(acc[py][px][3], x, wb.y);
                        ffma2(acc[py][px][4], x, wc.x);
                        ffma2(acc[py][px][5], x, wc.y);
                        ffma2(acc[py][px][6], x, wd.x);
                        ffma2(acc[py][px][7], x, wd.y);
                    }
            }

    float* ob = out + ((size_t)(b * Hp + oy) * Wp + ox) * 32 + r * 16;
    float o[16];
#pragma unroll
    for (int j = 0; j < 8; j++) {
        float s0 = 0.f, s1 = 0.f;
#pragma unroll
        for (int py = 0; py < 2; py++)
#pragma unroll
            for (int px = 0; px < 2; px++) {
                float lo, hi; unpack2(acc[py][px][j], lo, hi);
                s0 += LRELU(lo * BN_SCALEF);
                s1 += LRELU(hi * BN_SCALEF);
            }
        o[2 * j] = 0.25f * s0; o[2 * j + 1] = 0.25f * s1;
    }
#pragma unroll
    for (int v4 = 0; v4 < 4; v4++)
        ((float4*)ob)[v4] = make_float4(o[4 * v4], o[4 * v4 + 1], o[4 * v4 + 2], o[4 * v4 + 3]);
}

// ------ conv 3x3 (32->32) + BN + lrelu + pool; software-pipelined ---------
struct ColBuf2 { float4 c[2][4]; };

template<int RS>
__global__ __launch_bounds__(128) void conv_pool32(
    const float* __restrict__ in, float* __restrict__ out,
    const float* __restrict__ w, int B, int H, int W)
{
    constexpr int CO = 32 / RS;
    constexpr int NP = CO / 2;

    __shared__ __align__(16) float ws[9216];
    for (int i = threadIdx.x; i < 2304; i += blockDim.x)
        ((float4*)ws)[i] = __ldg((const float4*)w + i);
    __syncthreads();

    int Hp = H >> 1, Wp = W >> 1;
    int t = blockIdx.x * blockDim.x + threadIdx.x;
    int r = t & (RS - 1), q = t / RS;
    int ox = q % Wp; int tmp = q / Wp; int oy = tmp % Hp; int b = tmp / Hp;
    int cy0 = oy * 2, cx0 = ox * 2;

    const float* inb = in + (size_t)b * H * W * 32;
    size_t rowstride = (size_t)W * 32;

    bool vc[4];
    const float* colp[4];
#pragma unroll
    for (int j = 0; j < 4; j++) {
        int ix = cx0 - 1 + j;
        vc[j] = (ix >= 0) && (ix < W);
        colp[j] = inb + (size_t)ix * 32;
    }

    auto load = [&](int it, ColBuf2& cb) {
        int ky = it >> 3, c4 = it & 7;
        int iy0 = cy0 + ky - 1;
        bool v0 = (iy0 >= 0) && (iy0 < H);
        bool v1 = (iy0 + 1 < H);
        size_t off0 = (size_t)iy0 * rowstride;
        size_t off1 = off0 + rowstride;
        const float4 z = make_float4(0.f, 0.f, 0.f, 0.f);
#pragma unroll
        for (int j = 0; j < 4; j++) {
            cb.c[0][j] = (v0 && vc[j]) ? __ldg((const float4*)(colp[j] + off0) + c4) : z;
            cb.c[1][j] = (v1 && vc[j]) ? __ldg((const float4*)(colp[j] + off1) + c4) : z;
        }
    };

    ull acc[2][2][NP];
#pragma unroll
    for (int py = 0; py < 2; py++)
#pragma unroll
        for (int px = 0; px < 2; px++)
#pragma unroll
            for (int j = 0; j < NP; j++) acc[py][px][j] = 0ull;

    auto compute = [&](int it, ColBuf2& cb) {
        int ky = it >> 3, c4 = it & 7;
        const float* wbase = &ws[(ky * 3) * 1024 + (c4 * 4) * 32 + r * CO];
#pragma unroll
        for (int ci = 0; ci < 4; ci++)
#pragma unroll
            for (int kx = 0; kx < 3; kx++) {
                const ulonglong2* wp = (const ulonglong2*)(wbase + kx * 1024 + ci * 32);
                ull wv[NP];
#pragma unroll
                for (int g = 0; g < NP / 2; g++) {
                    ulonglong2 z = wp[g];
                    wv[2 * g] = z.x; wv[2 * g + 1] = z.y;
                }
#pragma unroll
                for (int py = 0; py < 2; py++)
#pragma unroll
                    for (int px = 0; px < 2; px++) {
                        ull x = pack2same(getc(cb.c[py][kx + px], ci));
#pragma unroll
                        for (int j = 0; j < NP; j++) ffma2(acc[py][px][j], x, wv[j]);
                    }
            }
    };

    ColBuf2 bufA, bufB;
    load(0, bufA);
#pragma unroll 1
    for (int it = 0; it < 24; it += 2) {
        load(it + 1, bufB);
        compute(it, bufA);
        if (it + 2 < 24) load(it + 2, bufA);
        compute(it + 1, bufB);
    }

    float* ob = out + ((size_t)(b * Hp + oy) * Wp + ox) * 32 + r * CO;
    float o[CO];
#pragma unroll
    for (int j = 0; j < NP; j++) {
        float s0 = 0.f, s1 = 0.f;
#pragma unroll
        for (int py = 0; py < 2; py++)
#pragma unroll
            for (int px = 0; px < 2; px++) {
                float lo, hi; unpack2(acc[py][px][j], lo, hi);
                s0 += LRELU(lo * BN_SCALEF);
                s1 += LRELU(hi * BN_SCALEF);
            }
        o[2 * j] = 0.25f * s0; o[2 * j + 1] = 0.25f * s1;
    }
#pragma unroll
    for (int v4 = 0; v4 < CO / 4; v4++)
        ((float4*)ob)[v4] = make_float4(o[4 * v4], o[4 * v4 + 1], o[4 * v4 + 2], o[4 * v4 + 3]);
}

// ------ conv 3x3 (32->32) + BN + lrelu (no pool); 2x2 tile x 8co ---------
// Weights read directly via __ldg (warp-uniform broadcast, L1-resident):
// no smem staging, no __syncthreads prologue.
__global__ __launch_bounds__(128) void conv32_2x2(
    const float* __restrict__ in, float* __restrict__ out,
    const float* __restrict__ w, int B, int H, int W)
{
    int Hp = H >> 1, Wp = W >> 1;
    int t = blockIdx.x * blockDim.x + threadIdx.x;
    int r = t & 3, q = t >> 2;                       // r: co group of 8
    int ox = q % Wp; int tmp = q / Wp; int oy = tmp % Hp; int b = tmp / Hp;
    int cy0 = oy * 2, cx0 = ox * 2;

    const float* inb = in + (size_t)b * H * W * 32;
    size_t rowstride = (size_t)W * 32;

    bool vc[4];
    const float* colp[4];
#pragma unroll
    for (int j = 0; j < 4; j++) {
        int ix = cx0 - 1 + j;
        vc[j] = (ix >= 0) && (ix < W);
        colp[j] = inb + (size_t)ix * 32;
    }

    auto load = [&](int it, ColBuf2& cb) {
        int ky = it >> 3, c4 = it & 7;
        int iy0 = cy0 + ky - 1;
        bool v0 = (iy0 >= 0) && (iy0 < H);
        bool v1 = (iy0 + 1 < H);
        size_t off0 = (size_t)iy0 * rowstride;
        size_t off1 = off0 + rowstride;
        const float4 z = make_float4(0.f, 0.f, 0.f, 0.f);
#pragma unroll
        for (int j = 0; j < 4; j++) {
            cb.c[0][j] = (v0 && vc[j]) ? __ldg((const float4*)(colp[j] + off0) + c4) : z;
            cb.c[1][j] = (v1 && vc[j]) ? __ldg((const float4*)(colp[j] + off1) + c4) : z;
        }
    };

    ull acc[2][2][4];
#pragma unroll
    for (int py = 0; py < 2; py++)
#pragma unroll
        for (int px = 0; px < 2; px++)
#pragma unroll
            for (int j = 0; j < 4; j++) acc[py][px][j] = 0ull;

    auto compute = [&](int it, ColBuf2& cb) {
        int ky = it >> 3, c4 = it & 7;
        const float* wbase = w + (ky * 3) * 1024 + (c4 * 4) * 32 + r * 8;
#pragma unroll
        for (int ci = 0; ci < 4; ci++)
#pragma unroll
            for (int kx = 0; kx < 3; kx++) {
                const ulonglong2* wp = (const ulonglong2*)(wbase + kx * 1024 + ci * 32);
                ulonglong2 w01 = __ldg(wp), w23 = __ldg(wp + 1);
#pragma unroll
                for (int py = 0; py < 2; py++)
#pragma unroll
                    for (int px = 0; px < 2; px++) {
                        ull x = pack2same(getc(cb.c[py][kx + px], ci));
                        ffma2(acc[py][px][0], x, w01.x);
                        ffma2(acc[py][px][1], x, w01.y);
                        ffma2(acc[py][px][2], x, w23.x);
                        ffma2(acc[py][px][3], x, w23.y);
                    }
            }
    };

    ColBuf2 bufA, bufB;
    load(0, bufA);
#pragma unroll 1
    for (int it = 0; it < 24; it += 2) {
        load(it + 1, bufB);
        compute(it, bufA);
        if (it + 2 < 24) load(it + 2, bufA);
        compute(it + 1, bufB);
    }

#pragma unroll
    for (int py = 0; py < 2; py++)
#pragma unroll
        for (int px = 0; px < 2; px++) {
            float* ob = out + ((size_t)(b * H + (cy0 + py)) * W + (cx0 + px)) * 32 + r * 8;
            float o[8];
#pragma unroll
            for (int j = 0; j < 4; j++) {
                float lo, hi; unpack2(acc[py][px][j], lo, hi);
                o[2 * j] = LRELU(lo * BN_SCALEF);
                o[2 * j + 1] = LRELU(hi * BN_SCALEF);
            }
            ((float4*)ob)[0] = make_float4(o[0], o[1], o[2], o[3]);
            ((float4*)ob)[1] = make_float4(o[4], o[5], o[6], o[7]);
        }
}

// ------ fw1 conv (2x2 tile x 8co, gmem weights) FUSED with pw0+pw1 -------
__global__ __launch_bounds__(128) void conv32_pw(
    const float* __restrict__ in, float* __restrict__ disp,
    const float* __restrict__ w, const float* __restrict__ pw0,
    const float* __restrict__ pw1, int B, int H, int W)
{
    __shared__ float w0t[1024];         // transposed pw0: [co][ci]
    __shared__ float w1s[64];
    for (int i = threadIdx.x; i < 1024; i += blockDim.x)
        w0t[(i & 31) * 32 + (i >> 5)] = __ldg(pw0 + i);
    if (threadIdx.x < 64) w1s[threadIdx.x] = __ldg(pw1 + threadIdx.x);
    __syncthreads();

    int Hp = H >> 1, Wp = W >> 1;
    int t = blockIdx.x * blockDim.x + threadIdx.x;
    int r = t & 3, q = t >> 2;
    int ox = q % Wp; int tmp = q / Wp; int oy = tmp % Hp; int b = tmp / Hp;
    int cy0 = oy * 2, cx0 = ox * 2;

    const float* inb = in + (size_t)b * H * W * 32;
    size_t rowstride = (size_t)W * 32;

    bool vc[4];
    const float* colp[4];
#pragma unroll
    for (int j = 0; j < 4; j++) {
        int ix = cx0 - 1 + j;
        vc[j] = (ix >= 0) && (ix < W);
        colp[j] = inb + (size_t)ix * 32;
    }

    auto load = [&](int it, ColBuf2& cb) {
        int ky = it >> 3, c4 = it & 7;
        int iy0 = cy0 + ky - 1;
        bool v0 = (iy0 >= 0) && (iy0 < H);
        bool v1 = (iy0 + 1 < H);
        size_t off0 = (size_t)iy0 * rowstride;
        size_t off1 = off0 + rowstride;
        const float4 z = make_float4(0.f, 0.f, 0.f, 0.f);
#pragma unroll
        for (int j = 0; j < 4; j++) {
            cb.c[0][j] = (v0 && vc[j]) ? __ldg((const float4*)(colp[j] + off0) + c4) : z;
            cb.c[1][j] = (v1 && vc[j]) ? __ldg((const float4*)(colp[j] + off1) + c4) : z;
        }
    };

    ull acc[2][2][4];
#pragma unroll
    for (int py = 0; py < 2; py++)
#pragma unroll
        for (int px = 0; px < 2; px++)
#pragma unroll
            for (int j = 0; j < 4; j++) acc[py][px][j] = 0ull;

    auto compute = [&](int it, ColBuf2& cb) {
        int ky = it >> 3, c4 = it & 7;
        const float* wbase = w + (ky * 3) * 1024 + (c4 * 4) * 32 + r * 8;
#pragma unroll
        for (int ci = 0; ci < 4; ci++)
#pragma unroll
            for (int kx = 0; kx < 3; kx++) {
                const ulonglong2* wp = (const ulonglong2*)(wbase + kx * 1024 + ci * 32);
                ulonglong2 w01 = __ldg(wp), w23 = __ldg(wp + 1);
#pragma unroll
                for (int py = 0; py < 2; py++)
#pragma unroll
                    for (int px = 0; px < 2; px++) {
                        ull x = pack2same(getc(cb.c[py][kx + px], ci));
                        ffma2(acc[py][px][0], x, w01.x);
                        ffma2(acc[py][px][1], x, w01.y);
                        ffma2(acc[py][px][2], x, w23.x);
                        ffma2(acc[py][px][3], x, w23.y);
                    }
            }
    };

    ColBuf2 bufA, bufB;
    load(0, bufA);
#pragma unroll 1
    for (int it = 0; it < 24; it += 2) {
        load(it + 1, bufB);
        compute(it, bufA);
        if (it + 2 < 24) load(it + 2, bufA);
        compute(it + 1, bufB);
    }

    // fw1 activations (this lane's 8 channels) for 4 pixels
    float y[2][2][8];
#pragma unroll
    for (int py = 0; py < 2; py++)
#pragma unroll
        for (int px = 0; px < 2; px++)
#pragma unroll
            for (int j = 0; j < 4; j++) {
                float lo, hi; unpack2(acc[py][px][j], lo, hi);
                y[py][px][2 * j] = LRELU(lo * BN_SCALEF);
                y[py][px][2 * j + 1] = LRELU(hi * BN_SCALEF);
            }

    // pw0 (lrelu, no BN) + pw1 via 4-lane butterfly per pixel
    float o0[2][2] = {{0.f, 0.f}, {0.f, 0.f}};
    float o1[2][2] = {{0.f, 0.f}, {0.f, 0.f}};
#pragma unroll 1
    for (int co = 0; co < 32; co++) {
        const float4* wrow = (const float4*)&w0t[co * 32 + r * 8];
        float4 wa = wrow[0], wb = wrow[1];
        float w1a = w1s[co * 2], w1b = w1s[co * 2 + 1];
#pragma unroll
        for (int py = 0; py < 2; py++)
#pragma unroll
            for (int px = 0; px < 2; px++) {
                float p = 0.f;
                p = fmaf(y[py][px][0], wa.x, p);
                p = fmaf(y[py][px][1], wa.y, p);
                p = fmaf(y[py][px][2], wa.z, p);
                p = fmaf(y[py][px][3], wa.w, p);
                p = fmaf(y[py][px][4], wb.x, p);
                p = fmaf(y[py][px][5], wb.y, p);
                p = fmaf(y[py][px][6], wb.z, p);
                p = fmaf(y[py][px][7], wb.w, p);
                p += __shfl_xor_sync(0xffffffffu, p, 1);
                p += __shfl_xor_sync(0xffffffffu, p, 2);
                float m = LRELU(p);
                o0[py][px] = fmaf(m, w1a, o0[py][px]);
                o1[py][px] = fmaf(m, w1b, o1[py][px]);
            }
    }

    if (r == 0) {
#pragma unroll
        for (int py = 0; py < 2; py++)
#pragma unroll
            for (int px = 0; px < 2; px++) {
                size_t di = (((size_t)b * H + (cy0 + py)) * W + (cx0 + px)) * 2;
                disp[di + 0] = o0[py][px];
                disp[di + 1] = o1[py][px];
            }
    }
}

// -------- B-spline upsample of disp (64x64 -> 512x512) + bilinear warp ---
__global__ __launch_bounds__(256) void bspline_warp(
    const float* __restrict__ disp, const float* __restrict__ movingp,
    float* __restrict__ out, int B, int H, int W)
{
    __shared__ float gd[4][7][2];

    int x = blockIdx.x * 32 + threadIdx.x;
    int y = blockIdx.y * 8 + threadIdx.y;
    int b = blockIdx.z;
    int jj = blockIdx.y;
    int ii0 = blockIdx.x * 4;

    {
        int tid = threadIdx.y * 32 + threadIdx.x;
        if (tid < 56) {
            int c = tid & 1, rest = tid >> 1;
            int col = rest % 7, row = rest / 7;
            int rj = jj - 1 + row, ri = ii0 - 1 + col;
            float v = 0.f;
            if (rj >= 0 && rj < 64 && ri >= 0 && ri < 64)
                v = __ldg(disp + (((size_t)b * 64 + rj) * 64 + ri) * 2 + c);
            gd[row][col][c] = v;
        }
    }
    __syncthreads();

    float xr = fminf((float)x * 0.125f, 63.f);
    float yr = fminf((float)y * 0.125f, 63.f);
    int ii = (int)floorf(xr);
    float u = xr * (1.f / 64.f), v = yr * (1.f / 64.f);

    float Bu[4], Bv[4];
    {
        float t2 = u * u, t3 = t2 * u;
        Bu[0] = -t3 + 3.f * t2 - 3.f * u + 1.f;
        Bu[1] = 3.f * t3 - 6.f * t2 + 4.f;
        Bu[2] = -3.f * t3 + 3.f * t2 + 3.f * u + 1.f;
        Bu[3] = t3;
    }
    {
        float t2 = v * v, t3 = t2 * v;
        Bv[0] = -t3 + 3.f * t2 - 3.f * v + 1.f;
        Bv[1] = 3.f * t3 - 6.f * t2 + 4.f;
        Bv[2] = -3.f * t3 + 3.f * t2 + 3.f * v + 1.f;
        Bv[3] = t3;
    }

    int ci = ii - ii0;
    float ic0 = 0.f, ic1 = 0.f;
#pragma unroll
    for (int m = 0; m < 4; m++) {
        float s0 = 0.f, s1 = 0.f;
#pragma unroll
        for (int n = 0; n < 4; n++) {
            s0 = fmaf(Bv[n], gd[m][ci + n][0], s0);
            s1 = fmaf(Bv[n], gd[m][ci + n][1], s1);
        }
        ic0 = fmaf(Bu[m], s0, ic0);
        ic1 = fmaf(Bu[m], s1, ic1);
    }

    float wx = ic0 + (float)x;
    float wy = ic1 + (float)y;

    float fx = floorf(wx), fy = floorf(wy);
    float x0 = fminf(fmaxf(fx, 0.f), (float)(W - 1));
    float x1 = fminf(fmaxf(fx + 1.f, 0.f), (float)(W - 1));
    float y0 = fminf(fmaxf(fy, 0.f), (float)(H - 1));
    float y1 = fminf(fmaxf(fy + 1.f, 0.f), (float)(H - 1));
    int x0i = (int)x0, x1i = (int)x1, y0i = (int)y0, y1i = (int)y1;

    const float* im = movingp + (size_t)b * H * W;
    float Q1 = __ldg(im + (size_t)y0i * W + x0i);
    float Q2 = __ldg(im + (size_t)y1i * W + x0i);
    float Q3 = __ldg(im + (size_t)y0i * W + x1i);
    float Q4 = __ldg(im + (size_t)y1i * W + x1i);

    const float eps = 1e-5f;
    float wxr = (x1 - wx) / (x1 - x0 + eps);
    float wxl = (wx - x0) / (x1 - x0 + eps);
    float R1 = wxr * Q1 + wxl * Q3;
    float R2 = wxr * Q2 + wxl * Q4;
    float o = (y1 - wy) / (y1 - y0 + eps) * R1 + (wy - y0) / (y1 - y0 + eps) * R2;

    out[(size_t)(b * H + y) * W + x] = o;
    float* grid = out + (size_t)B * H * W;
    grid[((size_t)(b * 2 + 0) * H + y) * W + x] = wx;
    grid[((size_t)(b * 2 + 1) * H + y) * W + x] = wy;
}

// --------------------------------- launch --------------------------------
extern "C" void kernel_launch(void* const* d_in, const int* in_sizes, int n_in,
                              void* d_out, int out_size)
{
    const float* fixedp  = (const float*)d_in[0];
    const float* movingp = (const float*)d_in[1];
    const float* w0  = (const float*)d_in[2];
    const float* w1  = (const float*)d_in[3];
    const float* w2  = (const float*)d_in[4];
    const float* fw0 = (const float*)d_in[5];
    const float* fw1 = (const float*)d_in[6];
    const float* pw0 = (const float*)d_in[7];
    const float* pw1 = (const float*)d_in[8];

    float *buf0, *buf1, *buf2, *buf3, *disp;
    cudaGetSymbolAddress((void**)&buf0, g_buf0);
    cudaGetSymbolAddress((void**)&buf1, g_buf1);
    cudaGetSymbolAddress((void**)&buf2, g_buf2);
    cudaGetSymbolAddress((void**)&buf3, g_buf3);
    cudaGetSymbolAddress((void**)&disp, g_disp);

    const int B = 4, H = 512, W = 512;

    conv_pool_first<<<(B * 256 * 256 * 2) / 128, 128>>>(fixedp, movingp, buf0, w0);
    conv_pool32<2><<<(B * 128 * 128 * 2) / 128, 128>>>(buf0, buf1, w1, B, 256, 256);
    conv_pool32<4><<<(B * 64 * 64 * 4) / 128, 128>>>(buf1, buf2, w2, B, 128, 128);
    // fw0: 2x2 tile x 8co x 4 co-groups, weights straight from gmem/L1
    conv32_2x2<<<(B * 32 * 32 * 4) / 128, 128>>>(buf2, buf3, fw0, B, 64, 64);
    // fw1 + pw0 + pw1 fused -> disp
    conv32_pw<<<(B * 32 * 32 * 4) / 128, 128>>>(buf3, disp, fw1, pw0, pw1, B, 64, 64);
    dim3 bw_grid(16, 64, B), bw_block(32, 8);
    bspline_warp<<<bw_grid, bw_block>>>(disp, movingp, (float*)d_out, B, H, W);
}

// round 15
// speedup vs baseline: 1.1247x; 1.1247x over previous
#include <cuda_runtime.h>
#include <cstdint>

#define BN_SCALEF 0.9995003746877732f
#define LRELU(v) ((v) > 0.f ? (v) : 0.2f * (v))

typedef unsigned long long ull;

// ---------------- f32x2 packed helpers ----------------
__device__ __forceinline__ ull pack2same(float x) {
    ull r; asm("mov.b64 %0, {%1, %1};" : "=l"(r) : "f"(x)); return r;
}
__device__ __forceinline__ void ffma2(ull& d, ull a, ull b) {
    asm("fma.rn.f32x2 %0, %1, %2, %0;" : "+l"(d) : "l"(a), "l"(b));
}
__device__ __forceinline__ void unpack2(ull v, float& lo, float& hi) {
    asm("mov.b64 {%0, %1}, %2;" : "=f"(lo), "=f"(hi) : "l"(v));
}
__device__ __forceinline__ float getc(float4 v, int i) {
    switch (i) { case 0: return v.x; case 1: return v.y; case 2: return v.z; default: return v.w; }
}

// ---------------- scratch (device globals; no allocation) ----------------
__device__ __align__(16) float g_buf0[4 * 256 * 256 * 32];
__device__ __align__(16) float g_buf1[4 * 128 * 128 * 32];
__device__ __align__(16) float g_buf2[4 * 64 * 64 * 32];
__device__ __align__(16) float g_buf3[4 * 64 * 64 * 32];
__device__ __align__(16) float g_disp[4 * 64 * 64 * 2];
__device__ unsigned g_barc[3];      // grid-barrier counters (rotating reset)

// ------ layer 0: conv 3x3 (2->32) + BN + lrelu + pool; 2x2 tile x 16co ----
__global__ __launch_bounds__(128) void conv_pool_first(
    const float* __restrict__ fixedp, const float* __restrict__ movingp,
    float* __restrict__ out, const float* __restrict__ w)
{
    __shared__ __align__(16) float ws[9 * 2 * 32];
    for (int i = threadIdx.x; i < 576; i += blockDim.x) ws[i] = w[i];
    __syncthreads();

    const int H = 512, W = 512, Hp = 256, Wp = 256;
    int t = blockIdx.x * blockDim.x + threadIdx.x;
    int r = t & 1, q = t >> 1;
    int ox = q % Wp; int tmp = q / Wp; int oy = tmp % Hp; int b = tmp / Hp;
    int cy0 = oy * 2, cx0 = ox * 2;

    float xin[2][4][4];
    const float* fb = fixedp  + (size_t)b * H * W;
    const float* mb = movingp + (size_t)b * H * W;
#pragma unroll
    for (int dy = 0; dy < 4; dy++) {
        int iy = cy0 - 1 + dy;
        bool vy = (iy >= 0) && (iy < H);
#pragma unroll
        for (int dx = 0; dx < 4; dx++) {
            int ix = cx0 - 1 + dx;
            bool v = vy && (ix >= 0) && (ix < W);
            xin[0][dy][dx] = v ? __ldg(fb + (size_t)iy * W + ix) : 0.f;
            xin[1][dy][dx] = v ? __ldg(mb + (size_t)iy * W + ix) : 0.f;
        }
    }

    ull acc[2][2][8];
#pragma unroll
    for (int py = 0; py < 2; py++)
#pragma unroll
        for (int px = 0; px < 2; px++)
#pragma unroll
            for (int j = 0; j < 8; j++) acc[py][px][j] = 0ull;

#pragma unroll
    for (int ky = 0; ky < 3; ky++)
#pragma unroll
        for (int kx = 0; kx < 3; kx++)
#pragma unroll
            for (int ci = 0; ci < 2; ci++) {
                const ulonglong2* wp =
                    (const ulonglong2*)&ws[((ky * 3 + kx) * 2 + ci) * 32 + r * 16];
                ulonglong2 wa = wp[0], wb = wp[1], wc = wp[2], wd = wp[3];
#pragma unroll
                for (int py = 0; py < 2; py++)
#pragma unroll
                    for (int px = 0; px < 2; px++) {
                        ull x = pack2same(xin[ci][ky + py][kx + px]);
                        ffma2(acc[py][px][0], x, wa.x);
                        ffma2(acc[py][px][1], x, wa.y);
                        ffma2(acc[py][px][2], x, wb.x);
                        ffma2(acc[py][px][3], x, wb.y);
                        ffma2(acc[py][px][4], x, wc.x);
                        ffma2(acc[py][px][5], x, wc.y);
                        ffma2(acc[py][px][6], x, wd.x);
                        ffma2(acc[py][px][7], x, wd.y);
                    }
            }

    float* ob = out + ((size_t)(b * Hp + oy) * Wp + ox) * 32 + r * 16;
    float o[16];
#pragma unroll
    for (int j = 0; j < 8; j++) {
        float s0 = 0.f, s1 = 0.f;
#pragma unroll
        for (int py = 0; py < 2; py++)
#pragma unroll
            for (int px = 0; px < 2; px++) {
                float lo, hi; unpack2(acc[py][px][j], lo, hi);
                s0 += LRELU(lo * BN_SCALEF);
                s1 += LRELU(hi * BN_SCALEF);
            }
        o[2 * j] = 0.25f * s0; o[2 * j + 1] = 0.25f * s1;
    }
#pragma unroll
    for (int v4 = 0; v4 < 4; v4++)
        ((float4*)ob)[v4] = make_float4(o[4 * v4], o[4 * v4 + 1], o[4 * v4 + 2], o[4 * v4 + 3]);
}

// ------ conv1: 3x3 (32->32) + BN + lrelu + pool; 2x2 tile x 16co ----------
struct ColBuf2 { float4 c[2][4]; };

__global__ __launch_bounds__(128) void conv_pool32_l1(
    const float* __restrict__ in, float* __restrict__ out,
    const float* __restrict__ w, int B, int H, int W)
{
    constexpr int RS = 2, CO = 16, NP = 8;

    __shared__ __align__(16) float ws[9216];
    for (int i = threadIdx.x; i < 2304; i += blockDim.x)
        ((float4*)ws)[i] = __ldg((const float4*)w + i);
    __syncthreads();

    int Hp = H >> 1, Wp = W >> 1;
    int t = blockIdx.x * blockDim.x + threadIdx.x;
    int r = t & (RS - 1), q = t / RS;
    int ox = q % Wp; int tmp = q / Wp; int oy = tmp % Hp; int b = tmp / Hp;
    int cy0 = oy * 2, cx0 = ox * 2;

    const float* inb = in + (size_t)b * H * W * 32;
    size_t rowstride = (size_t)W * 32;

    bool vc[4];
    const float* colp[4];
#pragma unroll
    for (int j = 0; j < 4; j++) {
        int ix = cx0 - 1 + j;
        vc[j] = (ix >= 0) && (ix < W);
        colp[j] = inb + (size_t)ix * 32;
    }

    auto load = [&](int it, ColBuf2& cb) {
        int ky = it >> 3, c4 = it & 7;
        int iy0 = cy0 + ky - 1;
        bool v0 = (iy0 >= 0) && (iy0 < H);
        bool v1 = (iy0 + 1 < H);
        size_t off0 = (size_t)iy0 * rowstride;
        size_t off1 = off0 + rowstride;
        const float4 z = make_float4(0.f, 0.f, 0.f, 0.f);
#pragma unroll
        for (int j = 0; j < 4; j++) {
            cb.c[0][j] = (v0 && vc[j]) ? __ldg((const float4*)(colp[j] + off0) + c4) : z;
            cb.c[1][j] = (v1 && vc[j]) ? __ldg((const float4*)(colp[j] + off1) + c4) : z;
        }
    };

    ull acc[2][2][NP];
#pragma unroll
    for (int py = 0; py < 2; py++)
#pragma unroll
        for (int px = 0; px < 2; px++)
#pragma unroll
            for (int j = 0; j < NP; j++) acc[py][px][j] = 0ull;

    auto compute = [&](int it, ColBuf2& cb) {
        int ky = it >> 3, c4 = it & 7;
        const float* wbase = &ws[(ky * 3) * 1024 + (c4 * 4) * 32 + r * CO];
#pragma unroll
        for (int ci = 0; ci < 4; ci++)
#pragma unroll
            for (int kx = 0; kx < 3; kx++) {
                const ulonglong2* wp = (const ulonglong2*)(wbase + kx * 1024 + ci * 32);
                ull wv[NP];
#pragma unroll
                for (int g = 0; g < NP / 2; g++) {
                    ulonglong2 z = wp[g];
                    wv[2 * g] = z.x; wv[2 * g + 1] = z.y;
                }
#pragma unroll
                for (int py = 0; py < 2; py++)
#pragma unroll
                    for (int px = 0; px < 2; px++) {
                        ull x = pack2same(getc(cb.c[py][kx + px], ci));
#pragma unroll
                        for (int j = 0; j < NP; j++) ffma2(acc[py][px][j], x, wv[j]);
                    }
            }
    };

    ColBuf2 bufA, bufB;
    load(0, bufA);
#pragma unroll 1
    for (int it = 0; it < 24; it += 2) {
        load(it + 1, bufB);
        compute(it, bufA);
        if (it + 2 < 24) load(it + 2, bufA);
        compute(it + 1, bufB);
    }

    float* ob = out + ((size_t)(b * Hp + oy) * Wp + ox) * 32 + r * CO;
    float o[CO];
#pragma unroll
    for (int j = 0; j < NP; j++) {
        float s0 = 0.f, s1 = 0.f;
#pragma unroll
        for (int py = 0; py < 2; py++)
#pragma unroll
            for (int px = 0; px < 2; px++) {
                float lo, hi; unpack2(acc[py][px][j], lo, hi);
                s0 += LRELU(lo * BN_SCALEF);
                s1 += LRELU(hi * BN_SCALEF);
            }
        o[2 * j] = 0.25f * s0; o[2 * j + 1] = 0.25f * s1;
    }
#pragma unroll
    for (int v4 = 0; v4 < CO / 4; v4++)
        ((float4*)ob)[v4] = make_float4(o[4 * v4], o[4 * v4 + 1], o[4 * v4 + 2], o[4 * v4 + 3]);
}

// ================== fused tail: conv2 -> fw0 -> fw1+pw -> bspline =========
// Software grid barrier: all blocks co-resident (grid sized by occupancy).
__device__ __forceinline__ void grid_bar(int k, int kreset, unsigned nb) {
    __threadfence();                     // publish this thread's writes
    __syncthreads();
    if (threadIdx.x == 0) {
        if (blockIdx.x == 0) {           // recycle counter for next replay
            g_barc[kreset] = 0;
            __threadfence();
        }
        atomicAdd(&g_barc[k], 1u);
        while (atomicAdd(&g_barc[k], 0u) < nb) __nanosleep(64);
        __threadfence();
    }
    __syncthreads();
}

__global__ __launch_bounds__(128) void fused_tail(
    const float* __restrict__ in1,      // conv1 output [4,128,128,32]
    float* __restrict__ buf2, float* __restrict__ buf3, float* __restrict__ disp,
    const float* __restrict__ w2, const float* __restrict__ fw0w,
    const float* __restrict__ fw1w, const float* __restrict__ pw0,
    const float* __restrict__ pw1,
    const float* __restrict__ movingp, float* __restrict__ outp,
    int nb)
{
    __shared__ __align__(16) float ws[9216];
    __shared__ float w0t[1024];
    __shared__ float w1s[64];
    __shared__ float gd[4][7][2];

    // ---------------- phase 0: conv2 (H=W=128 -> pooled 64x64), 512 tiles --
    for (int i = threadIdx.x; i < 2304; i += blockDim.x)
        ((float4*)ws)[i] = __ldg((const float4*)w2 + i);
    __syncthreads();

    {
        const int H = 128, W = 128, Hp = 64, Wp = 64;
        constexpr int RS = 4, CO = 8, NP = 4;
        size_t rowstride = (size_t)W * 32;
#pragma unroll 1
        for (int tile = blockIdx.x; tile < 512; tile += nb) {
            int t = tile * 128 + threadIdx.x;
            int r = t & (RS - 1), q = t / RS;
            int ox = q % Wp; int tmp = q / Wp; int oy = tmp % Hp; int b = tmp / Hp;
            int cy0 = oy * 2, cx0 = ox * 2;

            const float* inb = in1 + (size_t)b * H * W * 32;
            bool vc[4];
            const float* colp[4];
#pragma unroll
            for (int j = 0; j < 4; j++) {
                int ix = cx0 - 1 + j;
                vc[j] = (ix >= 0) && (ix < W);
                colp[j] = inb + (size_t)ix * 32;
            }

            auto load = [&](int it, ColBuf2& cb) {
                int ky = it >> 3, c4 = it & 7;
                int iy0 = cy0 + ky - 1;
                bool v0 = (iy0 >= 0) && (iy0 < H);
                bool v1 = (iy0 + 1 < H);
                size_t off0 = (size_t)iy0 * rowstride;
                size_t off1 = off0 + rowstride;
                const float4 z = make_float4(0.f, 0.f, 0.f, 0.f);
#pragma unroll
                for (int j = 0; j < 4; j++) {
                    cb.c[0][j] = (v0 && vc[j]) ? __ldg((const float4*)(colp[j] + off0) + c4) : z;
                    cb.c[1][j] = (v1 && vc[j]) ? __ldg((const float4*)(colp[j] + off1) + c4) : z;
                }
            };

            ull acc[2][2][NP];
#pragma unroll
            for (int py = 0; py < 2; py++)
#pragma unroll
                for (int px = 0; px < 2; px++)
#pragma unroll
                    for (int j = 0; j < NP; j++) acc[py][px][j] = 0ull;

            auto compute = [&](int it, ColBuf2& cb) {
                int ky = it >> 3, c4 = it & 7;
                const float* wbase = &ws[(ky * 3) * 1024 + (c4 * 4) * 32 + r * CO];
#pragma unroll
                for (int ci = 0; ci < 4; ci++)
#pragma unroll
                    for (int kx = 0; kx < 3; kx++) {
                        const ulonglong2* wp = (const ulonglong2*)(wbase + kx * 1024 + ci * 32);
                        ulonglong2 w01 = wp[0], w23 = wp[1];
#pragma unroll
                        for (int py = 0; py < 2; py++)
#pragma unroll
                            for (int px = 0; px < 2; px++) {
                                ull x = pack2same(getc(cb.c[py][kx + px], ci));
                                ffma2(acc[py][px][0], x, w01.x);
                                ffma2(acc[py][px][1], x, w01.y);
                                ffma2(acc[py][px][2], x, w23.x);
                                ffma2(acc[py][px][3], x, w23.y);
                            }
                    }
            };

            ColBuf2 bufA, bufB;
            load(0, bufA);
#pragma unroll 1
            for (int it = 0; it < 24; it += 2) {
                load(it + 1, bufB);
                compute(it, bufA);
                if (it + 2 < 24) load(it + 2, bufA);
                compute(it + 1, bufB);
            }

            float* ob = buf2 + ((size_t)(b * Hp + oy) * Wp + ox) * 32 + r * CO;
            float o[CO];
#pragma unroll
            for (int j = 0; j < NP; j++) {
                float s0 = 0.f, s1 = 0.f;
#pragma unroll
                for (int py = 0; py < 2; py++)
#pragma unroll
                    for (int px = 0; px < 2; px++) {
                        float lo, hi; unpack2(acc[py][px][j], lo, hi);
                        s0 += LRELU(lo * BN_SCALEF);
                        s1 += LRELU(hi * BN_SCALEF);
                    }
                o[2 * j] = 0.25f * s0; o[2 * j + 1] = 0.25f * s1;
            }
#pragma unroll
            for (int v4 = 0; v4 < CO / 4; v4++)
                ((float4*)ob)[v4] = make_float4(o[4 * v4], o[4 * v4 + 1], o[4 * v4 + 2], o[4 * v4 + 3]);
        }
    }

    grid_bar(0, 2, (unsigned)nb);

    // ---------------- phase 1: fw0 conv (64x64), 2x2 x 8co, 128 tiles ------
    for (int i = threadIdx.x; i < 2304; i += blockDim.x)
        ((float4*)ws)[i] = __ldg((const float4*)fw0w + i);
    __syncthreads();

    {
        const int H = 64, W = 64, Hp = 32, Wp = 32;
        size_t rowstride = (size_t)W * 32;
#pragma unroll 1
        for (int tile = blockIdx.x; tile < 128; tile += nb) {
            int t = tile * 128 + threadIdx.x;
            int r = t & 3, q = t >> 2;
            int ox = q % Wp; int tmp = q / Wp; int oy = tmp % Hp; int b = tmp / Hp;
            int cy0 = oy * 2, cx0 = ox * 2;

            const float* inb = buf2 + (size_t)b * H * W * 32;
            bool vc[4];
            const float* colp[4];
#pragma unroll
            for (int j = 0; j < 4; j++) {
                int ix = cx0 - 1 + j;
                vc[j] = (ix >= 0) && (ix < W);
                colp[j] = inb + (size_t)ix * 32;
            }

            auto load = [&](int it, ColBuf2& cb) {
                int ky = it >> 3, c4 = it & 7;
                int iy0 = cy0 + ky - 1;
                bool v0 = (iy0 >= 0) && (iy0 < H);
                bool v1 = (iy0 + 1 < H);
                size_t off0 = (size_t)iy0 * rowstride;
                size_t off1 = off0 + rowstride;
                const float4 z = make_float4(0.f, 0.f, 0.f, 0.f);
#pragma unroll
                for (int j = 0; j < 4; j++) {
                    cb.c[0][j] = (v0 && vc[j]) ? __ldg((const float4*)(colp[j] + off0) + c4) : z;
                    cb.c[1][j] = (v1 && vc[j]) ? __ldg((const float4*)(colp[j] + off1) + c4) : z;
                }
            };

            ull acc[2][2][4];
#pragma unroll
            for (int py = 0; py < 2; py++)
#pragma unroll
                for (int px = 0; px < 2; px++)
#pragma unroll
                    for (int j = 0; j < 4; j++) acc[py][px][j] = 0ull;

            auto compute = [&](int it, ColBuf2& cb) {
                int ky = it >> 3, c4 = it & 7;
                const float* wbase = &ws[(ky * 3) * 1024 + (c4 * 4) * 32 + r * 8];
#pragma unroll
                for (int ci = 0; ci < 4; ci++)
#pragma unroll
                    for (int kx = 0; kx < 3; kx++) {
                        const ulonglong2* wp = (const ulonglong2*)(wbase + kx * 1024 + ci * 32);
                        ulonglong2 w01 = wp[0], w23 = wp[1];
#pragma unroll
                        for (int py = 0; py < 2; py++)
#pragma unroll
                            for (int px = 0; px < 2; px++) {
                                ull x = pack2same(getc(cb.c[py][kx + px], ci));
                                ffma2(acc[py][px][0], x, w01.x);
                                ffma2(acc[py][px][1], x, w01.y);
                                ffma2(acc[py][px][2], x, w23.x);
                                ffma2(acc[py][px][3], x, w23.y);
                            }
                    }
            };

            ColBuf2 bufA, bufB;
            load(0, bufA);
#pragma unroll 1
            for (int it = 0; it < 24; it += 2) {
                load(it + 1, bufB);
                compute(it, bufA);
                if (it + 2 < 24) load(it + 2, bufA);
                compute(it + 1, bufB);
            }

#pragma unroll
            for (int py = 0; py < 2; py++)
#pragma unroll
                for (int px = 0; px < 2; px++) {
                    float* ob = buf3 + ((size_t)(b * H + (cy0 + py)) * W + (cx0 + px)) * 32 + r * 8;
                    float o[8];
#pragma unroll
                    for (int j = 0; j < 4; j++) {
                        float lo, hi; unpack2(acc[py][px][j], lo, hi);
                        o[2 * j] = LRELU(lo * BN_SCALEF);
                        o[2 * j + 1] = LRELU(hi * BN_SCALEF);
                    }
                    ((float4*)ob)[0] = make_float4(o[0], o[1], o[2], o[3]);
                    ((float4*)ob)[1] = make_float4(o[4], o[5], o[6], o[7]);
                }
        }
    }

    grid_bar(1, 0, (unsigned)nb);

    // ---------------- phase 2: fw1 conv + pw0 + pw1 -> disp, 128 tiles -----
    for (int i = threadIdx.x; i < 2304; i += blockDim.x)
        ((float4*)ws)[i] = __ldg((const float4*)fw1w + i);
    for (int i = threadIdx.x; i < 1024; i += blockDim.x)
        w0t[(i & 31) * 32 + (i >> 5)] = __ldg(pw0 + i);
    if (threadIdx.x < 64) w1s[threadIdx.x] = __ldg(pw1 + threadIdx.x);
    __syncthreads();

    {
        const int H = 64, W = 64, Hp = 32, Wp = 32;
        size_t rowstride = (size_t)W * 32;
#pragma unroll 1
        for (int tile = blockIdx.x; tile < 128; tile += nb) {
            int t = tile * 128 + threadIdx.x;
            int r = t & 3, q = t >> 2;
            int ox = q % Wp; int tmp = q / Wp; int oy = tmp % Hp; int b = tmp / Hp;
            int cy0 = oy * 2, cx0 = ox * 2;

            const float* inb = buf3 + (size_t)b * H * W * 32;
            bool vc[4];
            const float* colp[4];
#pragma unroll
            for (int j = 0; j < 4; j++) {
                int ix = cx0 - 1 + j;
                vc[j] = (ix >= 0) && (ix < W);
                colp[j] = inb + (size_t)ix * 32;
            }

            auto load = [&](int it, ColBuf2& cb) {
                int ky = it >> 3, c4 = it & 7;
                int iy0 = cy0 + ky - 1;
                bool v0 = (iy0 >= 0) && (iy0 < H);
                bool v1 = (iy0 + 1 < H);
                size_t off0 = (size_t)iy0 * rowstride;
                size_t off1 = off0 + rowstride;
                const float4 z = make_float4(0.f, 0.f, 0.f, 0.f);
#pragma unroll
                for (int j = 0; j < 4; j++) {
                    cb.c[0][j] = (v0 && vc[j]) ? __ldg((const float4*)(colp[j] + off0) + c4) : z;
                    cb.c[1][j] = (v1 && vc[j]) ? __ldg((const float4*)(colp[j] + off1) + c4) : z;
                }
            };

            ull acc[2][2][4];
#pragma unroll
            for (int py = 0; py < 2; py++)
#pragma unroll
                for (int px = 0; px < 2; px++)
#pragma unroll
                    for (int j = 0; j < 4; j++) acc[py][px][j] = 0ull;

            auto compute = [&](int it, ColBuf2& cb) {
                int ky = it >> 3, c4 = it & 7;
                const float* wbase = &ws[(ky * 3) * 1024 + (c4 * 4) * 32 + r * 8];
#pragma unroll
                for (int ci = 0; ci < 4; ci++)
#pragma unroll
                    for (int kx = 0; kx < 3; kx++) {
                        const ulonglong2* wp = (const ulonglong2*)(wbase + kx * 1024 + ci * 32);
                        ulonglong2 w01 = wp[0], w23 = wp[1];
#pragma unroll
                        for (int py = 0; py < 2; py++)
#pragma unroll
                            for (int px = 0; px < 2; px++) {
                                ull x = pack2same(getc(cb.c[py][kx + px], ci));
                                ffma2(acc[py][px][0], x, w01.x);
                                ffma2(acc[py][px][1], x, w01.y);
                                ffma2(acc[py][px][2], x, w23.x);
                                ffma2(acc[py][px][3], x, w23.y);
                            }
                    }
            };

            ColBuf2 bufA, bufB;
            load(0, bufA);
#pragma unroll 1
            for (int it = 0; it < 24; it += 2) {
                load(it + 1, bufB);
                compute(it, bufA);
                if (it + 2 < 24) load(it + 2, bufA);
                compute(it + 1, bufB);
            }

            float y[2][2][8];
#pragma unroll
            for (int py = 0; py < 2; py++)
#pragma unroll
                for (int px = 0; px < 2; px++)
#pragma unroll
                    for (int j = 0; j < 4; j++) {
                        float lo, hi; unpack2(acc[py][px][j], lo, hi);
                        y[py][px][2 * j] = LRELU(lo * BN_SCALEF);
                        y[py][px][2 * j + 1] = LRELU(hi * BN_SCALEF);
                    }

            float o0[2][2] = {{0.f, 0.f}, {0.f, 0.f}};
            float o1[2][2] = {{0.f, 0.f}, {0.f, 0.f}};
#pragma unroll 1
            for (int co = 0; co < 32; co++) {
                const float4* wrow = (const float4*)&w0t[co * 32 + r * 8];
                float4 wa = wrow[0], wb = wrow[1];
                float w1a = w1s[co * 2], w1b = w1s[co * 2 + 1];
#pragma unroll
                for (int py = 0; py < 2; py++)
#pragma unroll
                    for (int px = 0; px < 2; px++) {
                        float p = 0.f;
                        p = fmaf(y[py][px][0], wa.x, p);
                        p = fmaf(y[py][px][1], wa.y, p);
                        p = fmaf(y[py][px][2], wa.z, p);
                        p = fmaf(y[py][px][3], wa.w, p);
                        p = fmaf(y[py][px][4], wb.x, p);
                        p = fmaf(y[py][px][5], wb.y, p);
                        p = fmaf(y[py][px][6], wb.z, p);
                        p = fmaf(y[py][px][7], wb.w, p);
                        p += __shfl_xor_sync(0xffffffffu, p, 1);
                        p += __shfl_xor_sync(0xffffffffu, p, 2);
                        float m = LRELU(p);
                        o0[py][px] = fmaf(m, w1a, o0[py][px]);
                        o1[py][px] = fmaf(m, w1b, o1[py][px]);
                    }
            }

            if (r == 0) {
#pragma unroll
                for (int py = 0; py < 2; py++)
#pragma unroll
                    for (int px = 0; px < 2; px++) {
                        size_t di = (((size_t)b * H + (cy0 + py)) * W + (cx0 + px)) * 2;
                        disp[di + 0] = o0[py][px];
                        disp[di + 1] = o1[py][px];
                    }
            }
        }
    }

    grid_bar(2, 1, (unsigned)nb);

    // ---------------- phase 3: bspline + bilinear warp, 8192 tiles ---------
    {
        const int B = 4, H = 512, W = 512;
        int lane = threadIdx.x & 31, rowi = threadIdx.x >> 5;   // 32x4 pixel tile
#pragma unroll 1
        for (int tile = blockIdx.x; tile < 8192; tile += nb) {
            int b = tile >> 11;
            int rem = tile & 2047;
            int ty4 = rem >> 4;          // 4-row group (0..127)
            int tx = rem & 15;           // 32-col group
            int jj = ty4 >> 1;
            int ii0 = tx * 4;

            __syncthreads();             // protect gd from previous tile
            if (threadIdx.x < 56) {
                int c = threadIdx.x & 1, rest = threadIdx.x >> 1;
                int col = rest % 7, row = rest / 7;
                int rj = jj - 1 + row, ri = ii0 - 1 + col;
                float v = 0.f;
                if (rj >= 0 && rj < 64 && ri >= 0 && ri < 64)
                    v = __ldg(disp + (((size_t)b * 64 + rj) * 64 + ri) * 2 + c);
                gd[row][col][c] = v;
            }
            __syncthreads();

            int x = tx * 32 + lane;
            int y = ty4 * 4 + rowi;

            float xr = fminf((float)x * 0.125f, 63.f);
            float yr = fminf((float)y * 0.125f, 63.f);
            int ii = (int)floorf(xr);
            float u = xr * (1.f / 64.f), v = yr * (1.f / 64.f);

            float Bu[4], Bv[4];
            {
                float t2 = u * u, t3 = t2 * u;
                Bu[0] = -t3 + 3.f * t2 - 3.f * u + 1.f;
                Bu[1] = 3.f * t3 - 6.f * t2 + 4.f;
                Bu[2] = -3.f * t3 + 3.f * t2 + 3.f * u + 1.f;
                Bu[3] = t3;
            }
            {
                float t2 = v * v, t3 = t2 * v;
                Bv[0] = -t3 + 3.f * t2 - 3.f * v + 1.f;
                Bv[1] = 3.f * t3 - 6.f * t2 + 4.f;
                Bv[2] = -3.f * t3 + 3.f * t2 + 3.f * v + 1.f;
                Bv[3] = t3;
            }

            int ci = ii - ii0;
            float ic0 = 0.f, ic1 = 0.f;
#pragma unroll
            for (int m = 0; m < 4; m++) {
                float s0 = 0.f, s1 = 0.f;
#pragma unroll
                for (int n = 0; n < 4; n++) {
                    s0 = fmaf(Bv[n], gd[m][ci + n][0], s0);
                    s1 = fmaf(Bv[n], gd[m][ci + n][1], s1);
                }
                ic0 = fmaf(Bu[m], s0, ic0);
                ic1 = fmaf(Bu[m], s1, ic1);
            }

            float wx = ic0 + (float)x;
            float wy = ic1 + (float)y;

            float fx = floorf(wx), fy = floorf(wy);
            float x0 = fminf(fmaxf(fx, 0.f), (float)(W - 1));
            float x1 = fminf(fmaxf(fx + 1.f, 0.f), (float)(W - 1));
            float y0 = fminf(fmaxf(fy, 0.f), (float)(H - 1));
            float y1 = fminf(fmaxf(fy + 1.f, 0.f), (float)(H - 1));
            int x0i = (int)x0, x1i = (int)x1, y0i = (int)y0, y1i = (int)y1;

            const float* im = movingp + (size_t)b * H * W;
            float Q1 = __ldg(im + (size_t)y0i * W + x0i);
            float Q2 = __ldg(im + (size_t)y1i * W + x0i);
            float Q3 = __ldg(im + (size_t)y0i * W + x1i);
            float Q4 = __ldg(im + (size_t)y1i * W + x1i);

            const float eps = 1e-5f;
            float wxr = (x1 - wx) / (x1 - x0 + eps);
            float wxl = (wx - x0) / (x1 - x0 + eps);
            float R1 = wxr * Q1 + wxl * Q3;
            float R2 = wxr * Q2 + wxl * Q4;
            float o = (y1 - wy) / (y1 - y0 + eps) * R1 + (wy - y0) / (y1 - y0 + eps) * R2;

            outp[(size_t)(b * H + y) * W + x] = o;
            float* grid = outp + (size_t)B * H * W;
            grid[((size_t)(b * 2 + 0) * H + y) * W + x] = wx;
            grid[((size_t)(b * 2 + 1) * H + y) * W + x] = wy;
        }
    }
}

// --------------------------------- launch --------------------------------
extern "C" void kernel_launch(void* const* d_in, const int* in_sizes, int n_in,
                              void* d_out, int out_size)
{
    const float* fixedp  = (const float*)d_in[0];
    const float* movingp = (const float*)d_in[1];
    const float* w0  = (const float*)d_in[2];
    const float* w1  = (const float*)d_in[3];
    const float* w2  = (const float*)d_in[4];
    const float* fw0 = (const float*)d_in[5];
    const float* fw1 = (const float*)d_in[6];
    const float* pw0 = (const float*)d_in[7];
    const float* pw1 = (const float*)d_in[8];

    float *buf0, *buf1, *buf2, *buf3, *disp;
    cudaGetSymbolAddress((void**)&buf0, g_buf0);
    cudaGetSymbolAddress((void**)&buf1, g_buf1);
    cudaGetSymbolAddress((void**)&buf2, g_buf2);
    cudaGetSymbolAddress((void**)&buf3, g_buf3);
    cudaGetSymbolAddress((void**)&disp, g_disp);

    const int B = 4;

    // grid size for fused_tail: all blocks must be co-resident
    int dev = 0;
    cudaGetDevice(&dev);
    int nsm = 148;
    cudaDeviceGetAttribute(&nsm, cudaDevAttrMultiProcessorCount, dev);
    int perSM = 0;
    cudaOccupancyMaxActiveBlocksPerMultiprocessor(&perSM, fused_tail, 128, 0);
    if (perSM < 1) perSM = 1;
    int nb = perSM * nsm;
    if (nb > 512) nb = 512;

    conv_pool_first<<<(B * 256 * 256 * 2) / 128, 128>>>(fixedp, movingp, buf0, w0);
    conv_pool32_l1<<<(B * 128 * 128 * 2) / 128, 128>>>(buf0, buf1, w1, B, 256, 256);
    fused_tail<<<nb, 128>>>(buf1, buf2, buf3, disp, w2, fw0, fw1, pw0, pw1,
                            movingp, (float*)d_out, nb);
}

// round 16
// speedup vs baseline: 1.2541x; 1.1150x over previous
#include <cuda_runtime.h>
#include <cstdint>

#define BN_SCALEF 0.9995003746877732f
#define LRELU(v) ((v) > 0.f ? (v) : 0.2f * (v))

typedef unsigned long long ull;

// ---------------- f32x2 packed helpers ----------------
__device__ __forceinline__ ull pack2same(float x) {
    ull r; asm("mov.b64 %0, {%1, %1};" : "=l"(r) : "f"(x)); return r;
}
__device__ __forceinline__ void ffma2(ull& d, ull a, ull b) {
    asm("fma.rn.f32x2 %0, %1, %2, %0;" : "+l"(d) : "l"(a), "l"(b));
}
__device__ __forceinline__ void unpack2(ull v, float& lo, float& hi) {
    asm("mov.b64 {%0, %1}, %2;" : "=f"(lo), "=f"(hi) : "l"(v));
}
__device__ __forceinline__ float getc(float4 v, int i) {
    switch (i) { case 0: return v.x; case 1: return v.y; case 2: return v.z; default: return v.w; }
}

// ---------------- scratch (device globals; no allocation) ----------------
__device__ __align__(16) float g_buf0[4 * 256 * 256 * 32];
__device__ __align__(16) float g_buf1[4 * 128 * 128 * 32];
__device__ __align__(16) float g_buf2[4 * 64 * 64 * 32];
__device__ __align__(16) float g_buf3[4 * 64 * 64 * 32];
__device__ __align__(16) float g_disp[4 * 64 * 64 * 2];
__device__ unsigned g_ticket;          // monotone grid-barrier counter

// ------ layer 0: conv 3x3 (2->32) + BN + lrelu + pool; 2x2 tile x 16co ----
__global__ __launch_bounds__(128) void conv_pool_first(
    const float* __restrict__ fixedp, const float* __restrict__ movingp,
    float* __restrict__ out, const float* __restrict__ w)
{
    __shared__ __align__(16) float ws[9 * 2 * 32];
    for (int i = threadIdx.x; i < 576; i += blockDim.x) ws[i] = w[i];
    __syncthreads();

    const int H = 512, W = 512, Hp = 256, Wp = 256;
    int t = blockIdx.x * blockDim.x + threadIdx.x;
    int r = t & 1, q = t >> 1;
    int ox = q % Wp; int tmp = q / Wp; int oy = tmp % Hp; int b = tmp / Hp;
    int cy0 = oy * 2, cx0 = ox * 2;

    float xin[2][4][4];
    const float* fb = fixedp  + (size_t)b * H * W;
    const float* mb = movingp + (size_t)b * H * W;
#pragma unroll
    for (int dy = 0; dy < 4; dy++) {
        int iy = cy0 - 1 + dy;
        bool vy = (iy >= 0) && (iy < H);
#pragma unroll
        for (int dx = 0; dx < 4; dx++) {
            int ix = cx0 - 1 + dx;
            bool v = vy && (ix >= 0) && (ix < W);
            xin[0][dy][dx] = v ? __ldg(fb + (size_t)iy * W + ix) : 0.f;
            xin[1][dy][dx] = v ? __ldg(mb + (size_t)iy * W + ix) : 0.f;
        }
    }

    ull acc[2][2][8];
#pragma unroll
    for (int py = 0; py < 2; py++)
#pragma unroll
        for (int px = 0; px < 2; px++)
#pragma unroll
            for (int j = 0; j < 8; j++) acc[py][px][j] = 0ull;

#pragma unroll
    for (int ky = 0; ky < 3; ky++)
#pragma unroll
        for (int kx = 0; kx < 3; kx++)
#pragma unroll
            for (int ci = 0; ci < 2; ci++) {
                const ulonglong2* wp =
                    (const ulonglong2*)&ws[((ky * 3 + kx) * 2 + ci) * 32 + r * 16];
                ulonglong2 wa = wp[0], wb = wp[1], wc = wp[2], wd = wp[3];
#pragma unroll
                for (int py = 0; py < 2; py++)
#pragma unroll
                    for (int px = 0; px < 2; px++) {
                        ull x = pack2same(xin[ci][ky + py][kx + px]);
                        ffma2(acc[py][px][0], x, wa.x);
                        ffma2(acc[py][px][1], x, wa.y);
                        ffma2(acc[py][px][2], x, wb.x);
                        ffma2(acc[py][px][3], x, wb.y);
                        ffma2(acc[py][px][4], x, wc.x);
                        ffma2(acc[py][px][5], x, wc.y);
                        ffma2(acc[py][px][6], x, wd.x);
                        ffma2(acc[py][px][7], x, wd.y);
                    }
            }

    float* ob = out + ((size_t)(b * Hp + oy) * Wp + ox) * 32 + r * 16;
    float o[16];
#pragma unroll
    for (int j = 0; j < 8; j++) {
        float s0 = 0.f, s1 = 0.f;
#pragma unroll
        for (int py = 0; py < 2; py++)
#pragma unroll
            for (int px = 0; px < 2; px++) {
                float lo, hi; unpack2(acc[py][px][j], lo, hi);
                s0 += LRELU(lo * BN_SCALEF);
                s1 += LRELU(hi * BN_SCALEF);
            }
        o[2 * j] = 0.25f * s0; o[2 * j + 1] = 0.25f * s1;
    }
#pragma unroll
    for (int v4 = 0; v4 < 4; v4++)
        ((float4*)ob)[v4] = make_float4(o[4 * v4], o[4 * v4 + 1], o[4 * v4 + 2], o[4 * v4 + 3]);
}

// ------ conv 3x3 (32->32) + BN + lrelu + pool; software-pipelined ---------
struct ColBuf2 { float4 c[2][4]; };

template<int RS>
__global__ __launch_bounds__(128) void conv_pool32(
    const float* __restrict__ in, float* __restrict__ out,
    const float* __restrict__ w, int B, int H, int W)
{
    constexpr int CO = 32 / RS;
    constexpr int NP = CO / 2;

    __shared__ __align__(16) float ws[9216];
    for (int i = threadIdx.x; i < 2304; i += blockDim.x)
        ((float4*)ws)[i] = __ldg((const float4*)w + i);
    __syncthreads();

    int Hp = H >> 1, Wp = W >> 1;
    int t = blockIdx.x * blockDim.x + threadIdx.x;
    int r = t & (RS - 1), q = t / RS;
    int ox = q % Wp; int tmp = q / Wp; int oy = tmp % Hp; int b = tmp / Hp;
    int cy0 = oy * 2, cx0 = ox * 2;

    const float* inb = in + (size_t)b * H * W * 32;
    size_t rowstride = (size_t)W * 32;

    bool vc[4];
    const float* colp[4];
#pragma unroll
    for (int j = 0; j < 4; j++) {
        int ix = cx0 - 1 + j;
        vc[j] = (ix >= 0) && (ix < W);
        colp[j] = inb + (size_t)ix * 32;
    }

    auto load = [&](int it, ColBuf2& cb) {
        int ky = it >> 3, c4 = it & 7;
        int iy0 = cy0 + ky - 1;
        bool v0 = (iy0 >= 0) && (iy0 < H);
        bool v1 = (iy0 + 1 < H);
        size_t off0 = (size_t)iy0 * rowstride;
        size_t off1 = off0 + rowstride;
        const float4 z = make_float4(0.f, 0.f, 0.f, 0.f);
#pragma unroll
        for (int j = 0; j < 4; j++) {
            cb.c[0][j] = (v0 && vc[j]) ? __ldg((const float4*)(colp[j] + off0) + c4) : z;
            cb.c[1][j] = (v1 && vc[j]) ? __ldg((const float4*)(colp[j] + off1) + c4) : z;
        }
    };

    ull acc[2][2][NP];
#pragma unroll
    for (int py = 0; py < 2; py++)
#pragma unroll
        for (int px = 0; px < 2; px++)
#pragma unroll
            for (int j = 0; j < NP; j++) acc[py][px][j] = 0ull;

    auto compute = [&](int it, ColBuf2& cb) {
        int ky = it >> 3, c4 = it & 7;
        const float* wbase = &ws[(ky * 3) * 1024 + (c4 * 4) * 32 + r * CO];
#pragma unroll
        for (int ci = 0; ci < 4; ci++)
#pragma unroll
            for (int kx = 0; kx < 3; kx++) {
                const ulonglong2* wp = (const ulonglong2*)(wbase + kx * 1024 + ci * 32);
                ull wv[NP];
#pragma unroll
                for (int g = 0; g < NP / 2; g++) {
                    ulonglong2 z = wp[g];
                    wv[2 * g] = z.x; wv[2 * g + 1] = z.y;
                }
#pragma unroll
                for (int py = 0; py < 2; py++)
#pragma unroll
                    for (int px = 0; px < 2; px++) {
                        ull x = pack2same(getc(cb.c[py][kx + px], ci));
#pragma unroll
                        for (int j = 0; j < NP; j++) ffma2(acc[py][px][j], x, wv[j]);
                    }
            }
    };

    ColBuf2 bufA, bufB;
    load(0, bufA);
#pragma unroll 1
    for (int it = 0; it < 24; it += 2) {
        load(it + 1, bufB);
        compute(it, bufA);
        if (it + 2 < 24) load(it + 2, bufA);
        compute(it + 1, bufB);
    }

    float* ob = out + ((size_t)(b * Hp + oy) * Wp + ox) * 32 + r * CO;
    float o[CO];
#pragma unroll
    for (int j = 0; j < NP; j++) {
        float s0 = 0.f, s1 = 0.f;
#pragma unroll
        for (int py = 0; py < 2; py++)
#pragma unroll
            for (int px = 0; px < 2; px++) {
                float lo, hi; unpack2(acc[py][px][j], lo, hi);
                s0 += LRELU(lo * BN_SCALEF);
                s1 += LRELU(hi * BN_SCALEF);
            }
        o[2 * j] = 0.25f * s0; o[2 * j + 1] = 0.25f * s1;
    }
#pragma unroll
    for (int v4 = 0; v4 < CO / 4; v4++)
        ((float4*)ob)[v4] = make_float4(o[4 * v4], o[4 * v4 + 1], o[4 * v4 + 2], o[4 * v4 + 3]);
}

// ===== fused fw0 + (fw1 + pw0 + pw1): 128 blocks, one ticket barrier ======
// 128 blocks < 148 SMs and <= max-occupancy blocks: always co-resident.
__device__ __forceinline__ void ticket_barrier(int nb) {
    __threadfence();
    __syncthreads();
    if (threadIdx.x == 0) {
        unsigned old = atomicAdd(&g_ticket, 1u);
        unsigned target = (old / nb) * nb + nb;    // end of this barrier round
        while (atomicAdd(&g_ticket, 0u) < target) __nanosleep(64);
        __threadfence();
    }
    __syncthreads();
}

__global__ __launch_bounds__(128) void fw_fused(
    const float* __restrict__ in,       // conv2 output  [4,64,64,32]
    float* __restrict__ mid,            // fw0 output    [4,64,64,32]
    float* __restrict__ disp,           // [4,64,64,2]
    const float* __restrict__ fw0w, const float* __restrict__ fw1w,
    const float* __restrict__ pw0, const float* __restrict__ pw1,
    int nb)
{
    __shared__ __align__(16) float ws[9216];
    __shared__ float w0t[1024];
    __shared__ float w1s[64];

    const int H = 64, W = 64, Hp = 32, Wp = 32;
    size_t rowstride = (size_t)W * 32;

    int t = blockIdx.x * blockDim.x + threadIdx.x;
    int r = t & 3, q = t >> 2;
    int ox = q % Wp; int tmp = q / Wp; int oy = tmp % Hp; int b = tmp / Hp;
    int cy0 = oy * 2, cx0 = ox * 2;

    bool vc[4];
#pragma unroll
    for (int j = 0; j < 4; j++) {
        int ix = cx0 - 1 + j;
        vc[j] = (ix >= 0) && (ix < W);
    }

    // ---------------- phase A: fw0 conv -> mid -----------------------------
    for (int i = threadIdx.x; i < 2304; i += blockDim.x)
        ((float4*)ws)[i] = __ldg((const float4*)fw0w + i);
    __syncthreads();

    {
        const float* inb = in + (size_t)b * H * W * 32;
        const float* colp[4];
#pragma unroll
        for (int j = 0; j < 4; j++) colp[j] = inb + (size_t)(cx0 - 1 + j) * 32;

        auto load = [&](int it, ColBuf2& cb) {
            int ky = it >> 3, c4 = it & 7;
            int iy0 = cy0 + ky - 1;
            bool v0 = (iy0 >= 0) && (iy0 < H);
            bool v1 = (iy0 + 1 < H);
            size_t off0 = (size_t)iy0 * rowstride;
            size_t off1 = off0 + rowstride;
            const float4 z = make_float4(0.f, 0.f, 0.f, 0.f);
#pragma unroll
            for (int j = 0; j < 4; j++) {
                cb.c[0][j] = (v0 && vc[j]) ? __ldg((const float4*)(colp[j] + off0) + c4) : z;
                cb.c[1][j] = (v1 && vc[j]) ? __ldg((const float4*)(colp[j] + off1) + c4) : z;
            }
        };

        ull acc[2][2][4];
#pragma unroll
        for (int py = 0; py < 2; py++)
#pragma unroll
            for (int px = 0; px < 2; px++)
#pragma unroll
                for (int j = 0; j < 4; j++) acc[py][px][j] = 0ull;

        auto compute = [&](int it, ColBuf2& cb) {
            int ky = it >> 3, c4 = it & 7;
            const float* wbase = &ws[(ky * 3) * 1024 + (c4 * 4) * 32 + r * 8];
#pragma unroll
            for (int ci = 0; ci < 4; ci++)
#pragma unroll
                for (int kx = 0; kx < 3; kx++) {
                    const ulonglong2* wp = (const ulonglong2*)(wbase + kx * 1024 + ci * 32);
                    ulonglong2 w01 = wp[0], w23 = wp[1];
#pragma unroll
                    for (int py = 0; py < 2; py++)
#pragma unroll
                        for (int px = 0; px < 2; px++) {
                            ull x = pack2same(getc(cb.c[py][kx + px], ci));
                            ffma2(acc[py][px][0], x, w01.x);
                            ffma2(acc[py][px][1], x, w01.y);
                            ffma2(acc[py][px][2], x, w23.x);
                            ffma2(acc[py][px][3], x, w23.y);
                        }
                }
        };

        ColBuf2 bufA, bufB;
        load(0, bufA);
#pragma unroll 1
        for (int it = 0; it < 24; it += 2) {
            load(it + 1, bufB);
            compute(it, bufA);
            if (it + 2 < 24) load(it + 2, bufA);
            compute(it + 1, bufB);
        }

#pragma unroll
        for (int py = 0; py < 2; py++)
#pragma unroll
            for (int px = 0; px < 2; px++) {
                float* ob = mid + ((size_t)(b * H + (cy0 + py)) * W + (cx0 + px)) * 32 + r * 8;
                float o[8];
#pragma unroll
                for (int j = 0; j < 4; j++) {
                    float lo, hi; unpack2(acc[py][px][j], lo, hi);
                    o[2 * j] = LRELU(lo * BN_SCALEF);
                    o[2 * j + 1] = LRELU(hi * BN_SCALEF);
                }
                ((float4*)ob)[0] = make_float4(o[0], o[1], o[2], o[3]);
                ((float4*)ob)[1] = make_float4(o[4], o[5], o[6], o[7]);
            }
    }

    ticket_barrier(nb);

    // ---------------- phase B: fw1 conv + pw0 + pw1 -> disp ----------------
    for (int i = threadIdx.x; i < 2304; i += blockDim.x)
        ((float4*)ws)[i] = __ldg((const float4*)fw1w + i);
    for (int i = threadIdx.x; i < 1024; i += blockDim.x)
        w0t[(i & 31) * 32 + (i >> 5)] = __ldg(pw0 + i);
    if (threadIdx.x < 64) w1s[threadIdx.x] = __ldg(pw1 + threadIdx.x);
    __syncthreads();

    {
        const float* inb = mid + (size_t)b * H * W * 32;
        const float* colp[4];
#pragma unroll
        for (int j = 0; j < 4; j++) colp[j] = inb + (size_t)(cx0 - 1 + j) * 32;

        auto load = [&](int it, ColBuf2& cb) {
            int ky = it >> 3, c4 = it & 7;
            int iy0 = cy0 + ky - 1;
            bool v0 = (iy0 >= 0) && (iy0 < H);
            bool v1 = (iy0 + 1 < H);
            size_t off0 = (size_t)iy0 * rowstride;
            size_t off1 = off0 + rowstride;
            const float4 z = make_float4(0.f, 0.f, 0.f, 0.f);
#pragma unroll
            for (int j = 0; j < 4; j++) {
                cb.c[0][j] = (v0 && vc[j]) ? __ldg((const float4*)(colp[j] + off0) + c4) : z;
                cb.c[1][j] = (v1 && vc[j]) ? __ldg((const float4*)(colp[j] + off1) + c4) : z;
            }
        };

        ull acc[2][2][4];
#pragma unroll
        for (int py = 0; py < 2; py++)
#pragma unroll
            for (int px = 0; px < 2; px++)
#pragma unroll
                for (int j = 0; j < 4; j++) acc[py][px][j] = 0ull;

        auto compute = [&](int it, ColBuf2& cb) {
            int ky = it >> 3, c4 = it & 7;
            const float* wbase = &ws[(ky * 3) * 1024 + (c4 * 4) * 32 + r * 8];
#pragma unroll
            for (int ci = 0; ci < 4; ci++)
#pragma unroll
                for (int kx = 0; kx < 3; kx++) {
                    const ulonglong2* wp = (const ulonglong2*)(wbase + kx * 1024 + ci * 32);
                    ulonglong2 w01 = wp[0], w23 = wp[1];
#pragma unroll
                    for (int py = 0; py < 2; py++)
#pragma unroll
                        for (int px = 0; px < 2; px++) {
                            ull x = pack2same(getc(cb.c[py][kx + px], ci));
                            ffma2(acc[py][px][0], x, w01.x);
                            ffma2(acc[py][px][1], x, w01.y);
                            ffma2(acc[py][px][2], x, w23.x);
                            ffma2(acc[py][px][3], x, w23.y);
                        }
                }
        };

        ColBuf2 bufA, bufB;
        load(0, bufA);
#pragma unroll 1
        for (int it = 0; it < 24; it += 2) {
            load(it + 1, bufB);
            compute(it, bufA);
            if (it + 2 < 24) load(it + 2, bufA);
            compute(it + 1, bufB);
        }

        float y[2][2][8];
#pragma unroll
        for (int py = 0; py < 2; py++)
#pragma unroll
            for (int px = 0; px < 2; px++)
#pragma unroll
                for (int j = 0; j < 4; j++) {
                    float lo, hi; unpack2(acc[py][px][j], lo, hi);
                    y[py][px][2 * j] = LRELU(lo * BN_SCALEF);
                    y[py][px][2 * j + 1] = LRELU(hi * BN_SCALEF);
                }

        float o0[2][2] = {{0.f, 0.f}, {0.f, 0.f}};
        float o1[2][2] = {{0.f, 0.f}, {0.f, 0.f}};
#pragma unroll 1
        for (int co = 0; co < 32; co++) {
            const float4* wrow = (const float4*)&w0t[co * 32 + r * 8];
            float4 wa = wrow[0], wb = wrow[1];
            float w1a = w1s[co * 2], w1b = w1s[co * 2 + 1];
#pragma unroll
            for (int py = 0; py < 2; py++)
#pragma unroll
                for (int px = 0; px < 2; px++) {
                    float p = 0.f;
                    p = fmaf(y[py][px][0], wa.x, p);
                    p = fmaf(y[py][px][1], wa.y, p);
                    p = fmaf(y[py][px][2], wa.z, p);
                    p = fmaf(y[py][px][3], wa.w, p);
                    p = fmaf(y[py][px][4], wb.x, p);
                    p = fmaf(y[py][px][5], wb.y, p);
                    p = fmaf(y[py][px][6], wb.z, p);
                    p = fmaf(y[py][px][7], wb.w, p);
                    p += __shfl_xor_sync(0xffffffffu, p, 1);
                    p += __shfl_xor_sync(0xffffffffu, p, 2);
                    float m = LRELU(p);
                    o0[py][px] = fmaf(m, w1a, o0[py][px]);
                    o1[py][px] = fmaf(m, w1b, o1[py][px]);
                }
        }

        if (r == 0) {
#pragma unroll
            for (int py = 0; py < 2; py++)
#pragma unroll
                for (int px = 0; px < 2; px++) {
                    size_t di = (((size_t)b * H + (cy0 + py)) * W + (cx0 + px)) * 2;
                    disp[di + 0] = o0[py][px];
                    disp[di + 1] = o1[py][px];
                }
        }
    }
}

// -------- B-spline upsample of disp (64x64 -> 512x512) + bilinear warp ---
__global__ __launch_bounds__(256) void bspline_warp(
    const float* __restrict__ disp, const float* __restrict__ movingp,
    float* __restrict__ out, int B, int H, int W)
{
    __shared__ float gd[4][7][2];

    int x = blockIdx.x * 32 + threadIdx.x;
    int y = blockIdx.y * 8 + threadIdx.y;
    int b = blockIdx.z;
    int jj = blockIdx.y;
    int ii0 = blockIdx.x * 4;

    {
        int tid = threadIdx.y * 32 + threadIdx.x;
        if (tid < 56) {
            int c = tid & 1, rest = tid >> 1;
            int col = rest % 7, row = rest / 7;
            int rj = jj - 1 + row, ri = ii0 - 1 + col;
            float v = 0.f;
            if (rj >= 0 && rj < 64 && ri >= 0 && ri < 64)
                v = __ldg(disp + (((size_t)b * 64 + rj) * 64 + ri) * 2 + c);
            gd[row][col][c] = v;
        }
    }
    __syncthreads();

    float xr = fminf((float)x * 0.125f, 63.f);
    float yr = fminf((float)y * 0.125f, 63.f);
    int ii = (int)floorf(xr);
    float u = xr * (1.f / 64.f), v = yr * (1.f / 64.f);

    float Bu[4], Bv[4];
    {
        float t2 = u * u, t3 = t2 * u;
        Bu[0] = -t3 + 3.f * t2 - 3.f * u + 1.f;
        Bu[1] = 3.f * t3 - 6.f * t2 + 4.f;
        Bu[2] = -3.f * t3 + 3.f * t2 + 3.f * u + 1.f;
        Bu[3] = t3;
    }
    {
        float t2 = v * v, t3 = t2 * v;
        Bv[0] = -t3 + 3.f * t2 - 3.f * v + 1.f;
        Bv[1] = 3.f * t3 - 6.f * t2 + 4.f;
        Bv[2] = -3.f * t3 + 3.f * t2 + 3.f * v + 1.f;
        Bv[3] = t3;
    }

    int ci = ii - ii0;
    float ic0 = 0.f, ic1 = 0.f;
#pragma unroll
    for (int m = 0; m < 4; m++) {
        float s0 = 0.f, s1 = 0.f;
#pragma unroll
        for (int n = 0; n < 4; n++) {
            s0 = fmaf(Bv[n], gd[m][ci + n][0], s0);
            s1 = fmaf(Bv[n], gd[m][ci + n][1], s1);
        }
        ic0 = fmaf(Bu[m], s0, ic0);
        ic1 = fmaf(Bu[m], s1, ic1);
    }

    float wx = ic0 + (float)x;
    float wy = ic1 + (float)y;

    float fx = floorf(wx), fy = floorf(wy);
    float x0 = fminf(fmaxf(fx, 0.f), (float)(W - 1));
    float x1 = fminf(fmaxf(fx + 1.f, 0.f), (float)(W - 1));
    float y0 = fminf(fmaxf(fy, 0.f), (float)(H - 1));
    float y1 = fminf(fmaxf(fy + 1.f, 0.f), (float)(H - 1));
    int x0i = (int)x0, x1i = (int)x1, y0i = (int)y0, y1i = (int)y1;

    const float* im = movingp + (size_t)b * H * W;
    float Q1 = __ldg(im + (size_t)y0i * W + x0i);
    float Q2 = __ldg(im + (size_t)y1i * W + x0i);
    float Q3 = __ldg(im + (size_t)y0i * W + x1i);
    float Q4 = __ldg(im + (size_t)y1i * W + x1i);

    const float eps = 1e-5f;
    float wxr = (x1 - wx) / (x1 - x0 + eps);
    float wxl = (wx - x0) / (x1 - x0 + eps);
    float R1 = wxr * Q1 + wxl * Q3;
    float R2 = wxr * Q2 + wxl * Q4;
    float o = (y1 - wy) / (y1 - y0 + eps) * R1 + (wy - y0) / (y1 - y0 + eps) * R2;

    out[(size_t)(b * H + y) * W + x] = o;
    float* grid = out + (size_t)B * H * W;
    grid[((size_t)(b * 2 + 0) * H + y) * W + x] = wx;
    grid[((size_t)(b * 2 + 1) * H + y) * W + x] = wy;
}

// --------------------------------- launch --------------------------------
extern "C" void kernel_launch(void* const* d_in, const int* in_sizes, int n_in,
                              void* d_out, int out_size)
{
    const float* fixedp  = (const float*)d_in[0];
    const float* movingp = (const float*)d_in[1];
    const float* w0  = (const float*)d_in[2];
    const float* w1  = (const float*)d_in[3];
    const float* w2  = (const float*)d_in[4];
    const float* fw0 = (const float*)d_in[5];
    const float* fw1 = (const float*)d_in[6];
    const float* pw0 = (const float*)d_in[7];
    const float* pw1 = (const float*)d_in[8];

    float *buf0, *buf1, *buf2, *buf3, *disp;
    cudaGetSymbolAddress((void**)&buf0, g_buf0);
    cudaGetSymbolAddress((void**)&buf1, g_buf1);
    cudaGetSymbolAddress((void**)&buf2, g_buf2);
    cudaGetSymbolAddress((void**)&buf3, g_buf3);
    cudaGetSymbolAddress((void**)&disp, g_disp);

    const int B = 4, H = 512, W = 512;

    conv_pool_first<<<(B * 256 * 256 * 2) / 128, 128>>>(fixedp, movingp, buf0, w0);
    conv_pool32<2><<<(B * 128 * 128 * 2) / 128, 128>>>(buf0, buf1, w1, B, 256, 256);
    conv_pool32<4><<<(B * 64 * 64 * 4) / 128, 128>>>(buf1, buf2, w2, B, 128, 128);
    // fw0 + (fw1+pw) fused: 128 blocks (co-resident), one ticket barrier
    fw_fused<<<128, 128>>>(buf2, buf3, disp, fw0, fw1, pw0, pw1, 128);
    dim3 bw_grid(16, 64, B), bw_block(32, 8);
    bspline_warp<<<bw_grid, bw_block>>>(disp, movingp, (float*)d_out, B, H, W);
}